// round 14
// baseline (speedup 1.0000x reference)
#include <cuda_runtime.h>
#include <cstdint>
#include <cstddef>

#define B_      64
#define S_      784
#define SP_     792      // padded synapse rows (sentinel oh=0)
#define T_      500
#define N_      512
#define TP_     522
#define KS_     21
#define THETA_  40
#define CAPS_   128      // list slots per (b,tau): 8 groups x (15 real + 1 sentinel)
#define CAPR_   120      // real spike capacity (mean ~39, sd ~6)
#define NT_     32
#define TC_     128      // tau chunk
#define THREADS_ 1024
#define GRID_   148
#define PSTR_   544      // u16 pot row stride
#define ZP_     129      // z row stride (u32), odd -> conflict-free
#define NTICK_  (B_ * (N_ / NT_))     // 1024

__device__ int            g_cnt[B_ * T_];
__device__ unsigned short g_list[B_ * T_ * CAPS_];
__device__ unsigned       g_key[B_ * TP_];
__device__ unsigned       g_oh[S_ * N_];            // one-hot nibble words (v-1 encoding)
__device__ unsigned       g_ticket;

__device__ __forceinline__ int dp4a_(unsigned a, unsigned b, int c) {
    int r;
    asm("dp4a.u32.u32 %0, %1, %2, %3;" : "=r"(r) : "r"(a), "r"(b), "r"(c));
    return r;
}

// ---------------------------------------------------------------------------
__global__ void init_kernel() {
    int i = blockIdx.x * blockDim.x + threadIdx.x;
    if (i < B_ * T_)  g_cnt[i] = 0;
    if (i < B_ * TP_) g_key[i] = 0u;
    if (i == 0)       g_ticket = 0u;
}

__global__ void prepass_kernel(const float4* __restrict__ x) {
    const int T4 = T_ / 4;
    int idx = blockIdx.x * blockDim.x + threadIdx.x;
    if (idx >= B_ * S_ * T4) return;
    float4 v = x[idx];
    int t4 = idx % T4;
    int bs = idx / T4;
    int s  = bs % S_;
    int b  = bs / S_;
    int tb = t4 * 4;
    // Slot mapping: group g = c/15, pos = c%15 -> slot g*16 + pos.
#define EMIT_(dt, val) do { if ((val) != 0.0f) {                              \
        int row = b * T_ + tb + (dt);                                         \
        int c = atomicAdd(&g_cnt[row], 1);                                    \
        if (c < CAPR_) { int g = c / 15, p = c - g * 15;                      \
            g_list[(size_t)row * CAPS_ + g * 16 + p] = (unsigned short)s; } } } while (0)
    EMIT_(0, v.x); EMIT_(1, v.y); EMIT_(2, v.z); EMIT_(3, v.w);
#undef EMIT_
}

// Pad lists (sentinels in unused slots of used groups + 16th slot of each used
// group) and build one-hot weights. One kernel, two index ranges.
__global__ void pad_oh_kernel(const int* __restrict__ weight) {
    int i = blockIdx.x * blockDim.x + threadIdx.x;
    if (i < B_ * T_) {
        int cnt = g_cnt[i];
        cnt = cnt < CAPR_ ? cnt : CAPR_;
        int iters = (cnt + 14) / 15;
        unsigned short* lp = &g_list[(size_t)i * CAPS_];
        for (int c = cnt; c < iters * 15; c++) {
            int g = c / 15, p = c - g * 15;
            lp[g * 16 + p] = (unsigned short)784;
        }
        for (int g = 0; g < iters; g++) lp[g * 16 + 15] = (unsigned short)784;
    }
    if (i < N_ * S_) {
        int n = i / S_, s = i - n * S_;
        int w = weight[i] & 7;
        g_oh[s * N_ + n] = w ? (1u << (4 * (w - 1))) : 0u;
    }
}

// ---------------------------------------------------------------------------
// smem layout (bytes)
#define OFF_OH   0                      // u32 [SP_][32] one-hot tile             101376
#define OFF_POT  101376                 // u16 [NT_][PSTR_]                        34816
#define OFF_Z    136192                 // u32 [2 (L,H)][NT_][ZP_]                 33024
#define OFF_CNT  169216                 // i32 [T_]                                 2000
#define OFF_TLH  171216                 // uint2 [KS_]                               168
#define OFF_TK   171384                 // u32 ticket                                  8
#define SMEM_TOTAL 171392

__global__ void __launch_bounds__(THREADS_, 1) pot_kernel(const int* __restrict__ table) {
    extern __shared__ unsigned char smem[];
    unsigned*       oh     = (unsigned*)(smem + OFF_OH);
    unsigned short* pot_sm = (unsigned short*)(smem + OFF_POT);
    unsigned*       zL     = (unsigned*)(smem + OFF_Z);
    unsigned*       zH     = (unsigned*)(smem + OFF_Z) + NT_ * ZP_;
    int*            cnt_sm = (int*)(smem + OFF_CNT);
    uint2*          TLH    = (uint2*)(smem + OFF_TLH);
    unsigned*       tick   = (unsigned*)(smem + OFF_TK);

    const int tid = threadIdx.x;
    const int warpid = tid >> 5, lane = tid & 31;     // 32 warps
    const int slot = lane >> 3, sub = lane & 7;       // phase-1: tau slot / neuron quad
    const int tl = tid & 31, n2 = tid >> 5;           // phase-2: t group / neuron row

    // Table (time-flipped input): orig[v][j] = table[v][KS_-1-j].
    // v-1 packing: TLH.x bytes = orig[1..4][j], TLH.y bytes = orig[5..7][j],0.
    if (tid < KS_) {
        int j = tid;
        unsigned lo = 0, hi = 0;
#pragma unroll
        for (int v = 1; v <= 4; v++) lo |= ((unsigned)table[v * KS_ + (KS_ - 1 - j)]) << (8 * (v - 1));
#pragma unroll
        for (int v = 5; v <= 7; v++) hi |= ((unsigned)table[v * KS_ + (KS_ - 1 - j)]) << (8 * (v - 5));
        TLH[j] = make_uint2(lo, hi);
    }

    int prev_tile = -1;
    for (;;) {
        if (tid == 0) *tick = atomicAdd(&g_ticket, 1u);
        __syncthreads();                              // fences smem reuse
        unsigned my = *tick;
        if (my >= NTICK_) break;
        const int tile = (int)(my >> 6);              // tile-major ordering
        const int b    = (int)(my & 63u);
        const int n0   = tile * NT_;

        // Stage one-hot tile only when the tile changes.
        if (tile != prev_tile) {
            for (int i = tid; i < SP_ * 8; i += THREADS_) {
                int s = i >> 3, q = i & 7;
                uint4 v = make_uint4(0u, 0u, 0u, 0u);
                if (s < S_) v = *(const uint4*)&g_oh[s * N_ + n0 + 4 * q];
                ((uint4*)oh)[i] = v;
            }
            prev_tile = tile;
        }
        for (int i = tid; i < T_; i += THREADS_) {
            int c = g_cnt[b * T_ + i];
            cnt_sm[i] = c < CAPR_ ? c : CAPR_;
        }
        for (int i = tid; i < NT_ * PSTR_ / 2; i += THREADS_) ((unsigned*)pot_sm)[i] = 0u;
        __syncthreads();

        for (int c0 = 0; c0 < T_; c0 += TC_) {
            const int TCcur = (c0 + TC_ < T_) ? TC_ : (T_ - c0);   // 128 or 116

            // ---- Phase 1: warp = 4 taus; lane (slot,sub) serves 4 neurons via
            // one LDS.128 per spike-slot. Blocks of 16 slots = 15 real spikes
            // + 1 guaranteed sentinel (oh row 0) -> no masking, exact nibbles.
            {
                int ti = (warpid << 2) + slot;
                bool valid = ti < TCcur;               // warp-uniform (TCcur mult of 4)
                int cnt_mine = valid ? cnt_sm[c0 + ti] : 0;
                int iters_mine = (cnt_mine + 14) / 15;
                int iters_min = __reduce_min_sync(0xffffffffu, iters_mine);
                int iters_max = __reduce_max_sync(0xffffffffu, iters_mine);
                const uint4* lp4 = (const uint4*)&g_list[(size_t)(b * T_ + c0 + (valid ? ti : 0)) * CAPS_];
                const unsigned* ohb = oh + (sub << 2);
                unsigned zL0 = 0, zL1 = 0, zL2 = 0, zL3 = 0;
                unsigned zH0 = 0, zH1 = 0, zH2 = 0, zH3 = 0;
#define OHADD_(ss) do { uint4 o_ = *(const uint4*)(ohb + (ss) * 32);          \
        za += o_.x; zb += o_.y; zc += o_.z; zd += o_.w; } while (0)
#define BODY_(it_) do {                                                       \
        uint4 va = __ldg(lp4 + 2 * (it_));                                    \
        uint4 vb = __ldg(lp4 + 2 * (it_) + 1);                                \
        unsigned za = 0, zb = 0, zc = 0, zd = 0;                              \
        OHADD_(va.x & 0xFFFFu); OHADD_(va.x >> 16);                           \
        OHADD_(va.y & 0xFFFFu); OHADD_(va.y >> 16);                           \
        OHADD_(va.z & 0xFFFFu); OHADD_(va.z >> 16);                           \
        OHADD_(va.w & 0xFFFFu); OHADD_(va.w >> 16);                           \
        OHADD_(vb.x & 0xFFFFu); OHADD_(vb.x >> 16);                           \
        OHADD_(vb.y & 0xFFFFu); OHADD_(vb.y >> 16);                           \
        OHADD_(vb.z & 0xFFFFu); OHADD_(vb.z >> 16);                           \
        OHADD_(vb.w & 0xFFFFu); OHADD_(vb.w >> 16);                           \
        { unsigned a_ = za & 0x0F0F0F0Fu, b_ = (za >> 4) & 0x0F0F0F0Fu;       \
          zL0 += __byte_perm(a_, b_, 0x5140); zH0 += __byte_perm(a_, b_, 0x7362); } \
        { unsigned a_ = zb & 0x0F0F0F0Fu, b_ = (zb >> 4) & 0x0F0F0F0Fu;       \
          zL1 += __byte_perm(a_, b_, 0x5140); zH1 += __byte_perm(a_, b_, 0x7362); } \
        { unsigned a_ = zc & 0x0F0F0F0Fu, b_ = (zc >> 4) & 0x0F0F0F0Fu;       \
          zL2 += __byte_perm(a_, b_, 0x5140); zH2 += __byte_perm(a_, b_, 0x7362); } \
        { unsigned a_ = zd & 0x0F0F0F0Fu, b_ = (zd >> 4) & 0x0F0F0F0Fu;       \
          zL3 += __byte_perm(a_, b_, 0x5140); zH3 += __byte_perm(a_, b_, 0x7362); } } while (0)
                for (int it = 0; it < iters_min; it++) BODY_(it);   // warp-uniform
                for (int it = iters_min; it < iters_max; it++)      // short tail
                    if (it < iters_mine) BODY_(it);
#undef BODY_
#undef OHADD_
                if (valid) {
                    int nb = sub << 2;
                    zL[(nb + 0) * ZP_ + ti] = zL0; zH[(nb + 0) * ZP_ + ti] = zH0;
                    zL[(nb + 1) * ZP_ + ti] = zL1; zH[(nb + 1) * ZP_ + ti] = zH1;
                    zL[(nb + 2) * ZP_ + ti] = zL2; zH[(nb + 2) * ZP_ + ti] = zH2;
                    zL[(nb + 3) * ZP_ + ti] = zL3; zH[(nb + 3) * ZP_ + ti] = zH3;
                }
            }
            __syncthreads();

            // ---- Phase 2: 5-wide sliding-window stencil, conflict-free LDS.32.
            {
                const unsigned* zLr = zL + n2 * ZP_;
                const unsigned* zHr = zH + n2 * ZP_;
                const int tbase = 1 + 5 * tl;
#define ZLDL(ti_) (((unsigned)(ti_) < (unsigned)TCcur) ? zLr[(ti_)] : 0u)
#define ZLDH(ti_) (((unsigned)(ti_) < (unsigned)TCcur) ? zHr[(ti_)] : 0u)
                int acc0 = 0, acc1 = 0, acc2 = 0, acc3 = 0, acc4 = 0;
                unsigned l0, l1, l2, l3, l4, h0, h1, h2, h3, h4;
                l1 = ZLDL(tbase - 21); h1 = ZLDH(tbase - 21);
                l2 = ZLDL(tbase - 20); h2 = ZLDH(tbase - 20);
                l3 = ZLDL(tbase - 19); h3 = ZLDH(tbase - 19);
                l4 = ZLDL(tbase - 18); h4 = ZLDH(tbase - 18);
#pragma unroll
                for (int jj = 0; jj <= 20; jj++) {
                    const int j = 20 - jj;
                    l0 = l1; l1 = l2; l2 = l3; l3 = l4;
                    h0 = h1; h1 = h2; h2 = h3; h3 = h4;
                    l4 = ZLDL(tbase + 3 - j); h4 = ZLDH(tbase + 3 - j);
                    uint2 tlh = TLH[j];
                    acc0 = dp4a_(l0, tlh.x, acc0); acc0 = dp4a_(h0, tlh.y, acc0);
                    acc1 = dp4a_(l1, tlh.x, acc1); acc1 = dp4a_(h1, tlh.y, acc1);
                    acc2 = dp4a_(l2, tlh.x, acc2); acc2 = dp4a_(h2, tlh.y, acc2);
                    acc3 = dp4a_(l3, tlh.x, acc3); acc3 = dp4a_(h3, tlh.y, acc3);
                    acc4 = dp4a_(l4, tlh.x, acc4); acc4 = dp4a_(h4, tlh.y, acc4);
                }
#undef ZLDL
#undef ZLDH
                unsigned short* prow = &pot_sm[n2 * PSTR_ + c0];
                const int lim = TCcur + 20;
                if (tbase     <= lim) prow[tbase    ] = (unsigned short)(prow[tbase    ] + acc0);
                if (tbase + 1 <= lim) prow[tbase + 1] = (unsigned short)(prow[tbase + 1] + acc1);
                if (tbase + 2 <= lim) prow[tbase + 2] = (unsigned short)(prow[tbase + 2] + acc2);
                if (tbase + 3 <= lim) prow[tbase + 3] = (unsigned short)(prow[tbase + 3] + acc3);
                if (tbase + 4 <= lim) prow[tbase + 4] = (unsigned short)(prow[tbase + 4] + acc4);
            }
            __syncthreads();
        }

        // ---- Fused per-(b,t) argmax over this tile -> packed atomicMax.
        for (int t = tid; t < TP_; t += THREADS_) {
            int bv = -1, bn = 0;
#pragma unroll
            for (int nn = 0; nn < NT_; nn++) {
                int v = pot_sm[nn * PSTR_ + t];
                if (v > bv) { bv = v; bn = nn; }
            }
            unsigned key = ((unsigned)bv << 10) | (unsigned)(511 - (n0 + bn));
            atomicMax(&g_key[b * TP_ + t], key);
        }
        __syncthreads();
    }
}

// ---------------------------------------------------------------------------
__global__ void __launch_bounds__(32) scan_kernel(float* __restrict__ out) {
    __shared__ unsigned skey[TP_];
    __shared__ unsigned bm[17];
    int b = blockIdx.x;
    int lane = threadIdx.x;
#pragma unroll
    for (int w = 0; w < 17; w++) {
        int t = w * 32 + lane;
        unsigned key = (t < TP_) ? g_key[b * TP_ + t] : 0u;
        if (t < TP_) skey[t] = key;
        unsigned m = __ballot_sync(0xffffffffu, (int)(key >> 10) > THETA_);
        if (lane == 0) bm[w] = m;
    }
    __syncwarp();
    if (lane == 0) {
        int t = 0;
        while (t < TP_) {
            int w = t >> 5;
            unsigned m = bm[w] & (0xffffffffu << (t & 31));
            while (m == 0u && ++w < 17) m = bm[w];
            if (m == 0u) break;
            int t2 = (w << 5) + __ffs(m) - 1;
            if (t2 >= TP_) break;
            int n = 511 - (int)(skey[t2] & 1023u);
            out[((size_t)b * N_ + n) * TP_ + t2] = 1.0f;
            t = t2 + KS_ + 1;
        }
    }
}

// ---------------------------------------------------------------------------
extern "C" void kernel_launch(void* const* d_in, const int* in_sizes, int n_in,
                              void* d_out, int out_size) {
    const float* x      = (const float*)d_in[0];
    const int*   weight = (const int*)d_in[1];
    const int*   table  = (const int*)d_in[2];
    float*       out    = (float*)d_out;

    cudaFuncSetAttribute(pot_kernel, cudaFuncAttributeMaxDynamicSharedMemorySize, SMEM_TOTAL);

    cudaMemsetAsync(out, 0, (size_t)out_size * sizeof(float), 0);               // 1
    init_kernel<<<(B_ * TP_ + 255) / 256, 256>>>();                             // 2
    prepass_kernel<<<(B_ * S_ * (T_ / 4) + 255) / 256, 256>>>((const float4*)x);// 3
    pad_oh_kernel<<<(N_ * S_ + 255) / 256, 256>>>(weight);                      // 4

    pot_kernel<<<GRID_, THREADS_, SMEM_TOTAL>>>(table);                         // 5 -> profiled

    scan_kernel<<<B_, 32>>>(out);                                               // 6
}

// round 15
// speedup vs baseline: 1.0539x; 1.0539x over previous
#include <cuda_runtime.h>
#include <cstdint>
#include <cstddef>

#define B_      64
#define S_      784
#define SP_     792      // padded synapse rows (sentinel oh=0)
#define T_      500
#define N_      512
#define TP_     522
#define KS_     21
#define THETA_  40
#define CAP_    128
#define NT_     32
#define TC_     128      // tau chunk
#define NGRP_   125      // T_/4 warp-groups of 4 taus
#define THREADS_ 1024
#define GRID_   148
#define PSTR_   544      // u16 pot row stride
#define ZP_     129      // z row stride (u32), odd -> conflict-free
#define NTICK_  (B_ * (N_ / NT_))     // 1024

__device__ int            g_cnt[B_ * T_];
__device__ unsigned short g_list[B_ * T_ * CAP_];
__device__ unsigned       g_key[B_ * TP_];
__device__ unsigned       g_oh[S_ * N_];            // one-hot nibble words (v-1 encoding)
__device__ unsigned       g_ticket;

__device__ __forceinline__ int dp4a_(unsigned a, unsigned b, int c) {
    int r;
    asm("dp4a.u32.u32 %0, %1, %2, %3;" : "=r"(r) : "r"(a), "r"(b), "r"(c));
    return r;
}

// ---------------------------------------------------------------------------
__global__ void init_kernel() {
    int i = blockIdx.x * blockDim.x + threadIdx.x;
    if (i < B_ * T_)  g_cnt[i] = 0;
    if (i < B_ * TP_) g_key[i] = 0u;
    if (i == 0)       g_ticket = 0u;
}

__global__ void prepass_kernel(const float4* __restrict__ x) {
    const int T4 = T_ / 4;
    int idx = blockIdx.x * blockDim.x + threadIdx.x;
    if (idx >= B_ * S_ * T4) return;
    float4 v = x[idx];
    int t4 = idx % T4;
    int bs = idx / T4;
    int s  = bs % S_;
    int b  = bs / S_;
    int tb = t4 * 4;
    if (v.x != 0.0f) { int c = atomicAdd(&g_cnt[b * T_ + tb + 0], 1); if (c < CAP_) g_list[(b * T_ + tb + 0) * CAP_ + c] = (unsigned short)s; }
    if (v.y != 0.0f) { int c = atomicAdd(&g_cnt[b * T_ + tb + 1], 1); if (c < CAP_) g_list[(b * T_ + tb + 1) * CAP_ + c] = (unsigned short)s; }
    if (v.z != 0.0f) { int c = atomicAdd(&g_cnt[b * T_ + tb + 2], 1); if (c < CAP_) g_list[(b * T_ + tb + 2) * CAP_ + c] = (unsigned short)s; }
    if (v.w != 0.0f) { int c = atomicAdd(&g_cnt[b * T_ + tb + 3], 1); if (c < CAP_) g_list[(b * T_ + tb + 3) * CAP_ + c] = (unsigned short)s; }
}

// Pad each list with sentinels up to its warp-group's max count (rounded to 8)
// so the histogram's uniform group-max loop never reads uninitialized slots.
// Also builds one-hot weights (second index range).
__global__ void pad_oh_kernel(const int* __restrict__ weight) {
    int i = blockIdx.x * blockDim.x + threadIdx.x;
    if (i < B_ * T_) {
        int tau = i % T_;
        int base = i - (tau & 3);                     // group start row (T_ % 4 == 0)
        int gmax = 0;
#pragma unroll
        for (int d = 0; d < 4; d++) {
            int c = g_cnt[base + d];
            c = c < CAP_ ? c : CAP_;
            gmax = c > gmax ? c : gmax;
        }
        int cnt = g_cnt[i];
        cnt = cnt < CAP_ ? cnt : CAP_;
        int end = (gmax + 7) & ~7;
        unsigned short* lp = &g_list[(size_t)i * CAP_];
        for (int c = cnt; c < end; c++) lp[c] = (unsigned short)784;
    }
    if (i < N_ * S_) {
        int n = i / S_, s = i - n * S_;
        int w = weight[i] & 7;
        g_oh[s * N_ + n] = w ? (1u << (4 * (w - 1))) : 0u;
    }
}

// ---------------------------------------------------------------------------
// smem layout (bytes)
#define OFF_OH   0                      // u32 [SP_][32] one-hot tile             101376
#define OFF_POT  101376                 // u16 [NT_][PSTR_]                        34816
#define OFF_Z    136192                 // u32 [2 (L,H)][NT_][ZP_]                 33024
#define OFF_C4   169216                 // i32 [128] group max counts                512
#define OFF_TLH  169728                 // uint2 [KS_]                               168
#define OFF_TK   169896                 // u32 ticket                                  8
#define SMEM_TOTAL 169904

__global__ void __launch_bounds__(THREADS_, 1) pot_kernel(const int* __restrict__ table) {
    extern __shared__ unsigned char smem[];
    unsigned*       oh     = (unsigned*)(smem + OFF_OH);
    unsigned short* pot_sm = (unsigned short*)(smem + OFF_POT);
    unsigned*       zL     = (unsigned*)(smem + OFF_Z);
    unsigned*       zH     = (unsigned*)(smem + OFF_Z) + NT_ * ZP_;
    int*            c4     = (int*)(smem + OFF_C4);
    uint2*          TLH    = (uint2*)(smem + OFF_TLH);
    unsigned*       tick   = (unsigned*)(smem + OFF_TK);

    const int tid = threadIdx.x;
    const int warpid = tid >> 5, lane = tid & 31;     // 32 warps
    const int slot = lane >> 3, sub = lane & 7;       // phase-1: tau slot / neuron quad
    const int tl = tid & 31, n2 = tid >> 5;           // phase-2: t group / neuron row

    // Table (time-flipped input): orig[v][j] = table[v][KS_-1-j].
    // v-1 packing: TLH.x bytes = orig[1..4][j], TLH.y = orig[5..7][j],0.
    if (tid < KS_) {
        int j = tid;
        unsigned lo = 0, hi = 0;
#pragma unroll
        for (int v = 1; v <= 4; v++) lo |= ((unsigned)table[v * KS_ + (KS_ - 1 - j)]) << (8 * (v - 1));
#pragma unroll
        for (int v = 5; v <= 7; v++) hi |= ((unsigned)table[v * KS_ + (KS_ - 1 - j)]) << (8 * (v - 5));
        TLH[j] = make_uint2(lo, hi);
    }

    int prev_tile = -1;
    for (;;) {
        if (tid == 0) *tick = atomicAdd(&g_ticket, 1u);
        __syncthreads();                              // fences smem reuse
        unsigned my = *tick;
        if (my >= NTICK_) break;
        const int tile = (int)(my >> 6);              // tile-major ordering
        const int b    = (int)(my & 63u);
        const int n0   = tile * NT_;

        // Stage one-hot tile only when the tile changes.
        if (tile != prev_tile) {
            for (int i = tid; i < SP_ * 8; i += THREADS_) {
                int s = i >> 3, q = i & 7;
                uint4 v = make_uint4(0u, 0u, 0u, 0u);
                if (s < S_) v = *(const uint4*)&g_oh[s * N_ + n0 + 4 * q];
                ((uint4*)oh)[i] = v;
            }
            prev_tile = tile;
        }
        // Per-group max spike counts (125 groups of 4 taus).
        for (int i = tid; i < NGRP_; i += THREADS_) {
            int m = 0;
#pragma unroll
            for (int d = 0; d < 4; d++) {
                int c = g_cnt[b * T_ + 4 * i + d];
                c = c < CAP_ ? c : CAP_;
                m = c > m ? c : m;
            }
            c4[i] = m;
        }
        for (int i = tid; i < NT_ * PSTR_ / 2; i += THREADS_) ((unsigned*)pot_sm)[i] = 0u;
        __syncthreads();

        for (int c0 = 0; c0 < T_; c0 += TC_) {
            const int TCcur = (c0 + TC_ < T_) ? TC_ : (T_ - c0);   // 128 or 116

            // ---- Phase 1: warp = 4 taus; lane (slot,sub) serves 4 neurons via
            // one LDS.128 per spike. Uniform group-max trip count (lists padded
            // with sentinels to group max), LDG prefetch hides list latency.
            {
                int ti = (warpid << 2) + slot;
                if (ti < TCcur) {                      // warp-uniform (TCcur mult of 4)
                    int iters = (c4[(c0 >> 2) + warpid] + 7) >> 3;
                    const uint4* lp4 = (const uint4*)&g_list[(size_t)(b * T_ + c0 + ti) * CAP_];
                    const unsigned* ohb = oh + (sub << 2);
                    unsigned zL0 = 0, zL1 = 0, zL2 = 0, zL3 = 0;
                    unsigned zH0 = 0, zH1 = 0, zH2 = 0, zH3 = 0;
                    uint4 nxt = make_uint4(0x03100310u, 0x03100310u, 0x03100310u, 0x03100310u);
                    if (iters > 0) nxt = __ldg(lp4);
                    for (int it = 0; it < iters; it++) {
                        uint4 v4 = nxt;
                        if (it + 1 < iters) nxt = __ldg(lp4 + it + 1);
                        unsigned za = 0, zb = 0, zc = 0, zd = 0;
#define OHADD_(ss) do { uint4 o_ = *(const uint4*)(ohb + (ss) * 32);          \
        za += o_.x; zb += o_.y; zc += o_.z; zd += o_.w; } while (0)
                        OHADD_(v4.x & 0xFFFFu); OHADD_(v4.x >> 16);
                        OHADD_(v4.y & 0xFFFFu); OHADD_(v4.y >> 16);
                        OHADD_(v4.z & 0xFFFFu); OHADD_(v4.z >> 16);
                        OHADD_(v4.w & 0xFFFFu); OHADD_(v4.w >> 16);
#undef OHADD_
#define EXP_(z, L, H) do { unsigned a_ = (z) & 0x0F0F0F0Fu;                   \
        unsigned b_ = ((z) >> 4) & 0x0F0F0F0Fu;                               \
        L += __byte_perm(a_, b_, 0x5140); H += __byte_perm(a_, b_, 0x7362); } while (0)
                        EXP_(za, zL0, zH0); EXP_(zb, zL1, zH1);
                        EXP_(zc, zL2, zH2); EXP_(zd, zL3, zH3);
#undef EXP_
                    }
                    int nb = sub << 2;
                    zL[(nb + 0) * ZP_ + ti] = zL0; zH[(nb + 0) * ZP_ + ti] = zH0;
                    zL[(nb + 1) * ZP_ + ti] = zL1; zH[(nb + 1) * ZP_ + ti] = zH1;
                    zL[(nb + 2) * ZP_ + ti] = zL2; zH[(nb + 2) * ZP_ + ti] = zH2;
                    zL[(nb + 3) * ZP_ + ti] = zL3; zH[(nb + 3) * ZP_ + ti] = zH3;
                }
            }
            __syncthreads();

            // ---- Phase 2: 5-wide sliding-window stencil, conflict-free LDS.32.
            {
                const unsigned* zLr = zL + n2 * ZP_;
                const unsigned* zHr = zH + n2 * ZP_;
                const int tbase = 1 + 5 * tl;
#define ZLDL(ti_) (((unsigned)(ti_) < (unsigned)TCcur) ? zLr[(ti_)] : 0u)
#define ZLDH(ti_) (((unsigned)(ti_) < (unsigned)TCcur) ? zHr[(ti_)] : 0u)
                int acc0 = 0, acc1 = 0, acc2 = 0, acc3 = 0, acc4 = 0;
                unsigned l0, l1, l2, l3, l4, h0, h1, h2, h3, h4;
                l1 = ZLDL(tbase - 21); h1 = ZLDH(tbase - 21);
                l2 = ZLDL(tbase - 20); h2 = ZLDH(tbase - 20);
                l3 = ZLDL(tbase - 19); h3 = ZLDH(tbase - 19);
                l4 = ZLDL(tbase - 18); h4 = ZLDH(tbase - 18);
#pragma unroll
                for (int jj = 0; jj <= 20; jj++) {
                    const int j = 20 - jj;
                    l0 = l1; l1 = l2; l2 = l3; l3 = l4;
                    h0 = h1; h1 = h2; h2 = h3; h3 = h4;
                    l4 = ZLDL(tbase + 3 - j); h4 = ZLDH(tbase + 3 - j);
                    uint2 tlh = TLH[j];
                    acc0 = dp4a_(l0, tlh.x, acc0); acc0 = dp4a_(h0, tlh.y, acc0);
                    acc1 = dp4a_(l1, tlh.x, acc1); acc1 = dp4a_(h1, tlh.y, acc1);
                    acc2 = dp4a_(l2, tlh.x, acc2); acc2 = dp4a_(h2, tlh.y, acc2);
                    acc3 = dp4a_(l3, tlh.x, acc3); acc3 = dp4a_(h3, tlh.y, acc3);
                    acc4 = dp4a_(l4, tlh.x, acc4); acc4 = dp4a_(h4, tlh.y, acc4);
                }
#undef ZLDL
#undef ZLDH
                unsigned short* prow = &pot_sm[n2 * PSTR_ + c0];
                const int lim = TCcur + 20;
                if (tbase     <= lim) prow[tbase    ] = (unsigned short)(prow[tbase    ] + acc0);
                if (tbase + 1 <= lim) prow[tbase + 1] = (unsigned short)(prow[tbase + 1] + acc1);
                if (tbase + 2 <= lim) prow[tbase + 2] = (unsigned short)(prow[tbase + 2] + acc2);
                if (tbase + 3 <= lim) prow[tbase + 3] = (unsigned short)(prow[tbase + 3] + acc3);
                if (tbase + 4 <= lim) prow[tbase + 4] = (unsigned short)(prow[tbase + 4] + acc4);
            }
            __syncthreads();
        }

        // ---- Fused per-(b,t) argmax over this tile -> packed atomicMax.
        for (int t = tid; t < TP_; t += THREADS_) {
            int bv = -1, bn = 0;
#pragma unroll
            for (int nn = 0; nn < NT_; nn++) {
                int v = pot_sm[nn * PSTR_ + t];
                if (v > bv) { bv = v; bn = nn; }
            }
            unsigned key = ((unsigned)bv << 10) | (unsigned)(511 - (n0 + bn));
            atomicMax(&g_key[b * TP_ + t], key);
        }
        __syncthreads();
    }
}

// ---------------------------------------------------------------------------
__global__ void __launch_bounds__(32) scan_kernel(float* __restrict__ out) {
    __shared__ unsigned skey[TP_];
    __shared__ unsigned bm[17];
    int b = blockIdx.x;
    int lane = threadIdx.x;
#pragma unroll
    for (int w = 0; w < 17; w++) {
        int t = w * 32 + lane;
        unsigned key = (t < TP_) ? g_key[b * TP_ + t] : 0u;
        if (t < TP_) skey[t] = key;
        unsigned m = __ballot_sync(0xffffffffu, (int)(key >> 10) > THETA_);
        if (lane == 0) bm[w] = m;
    }
    __syncwarp();
    if (lane == 0) {
        int t = 0;
        while (t < TP_) {
            int w = t >> 5;
            unsigned m = bm[w] & (0xffffffffu << (t & 31));
            while (m == 0u && ++w < 17) m = bm[w];
            if (m == 0u) break;
            int t2 = (w << 5) + __ffs(m) - 1;
            if (t2 >= TP_) break;
            int n = 511 - (int)(skey[t2] & 1023u);
            out[((size_t)b * N_ + n) * TP_ + t2] = 1.0f;
            t = t2 + KS_ + 1;
        }
    }
}

// ---------------------------------------------------------------------------
extern "C" void kernel_launch(void* const* d_in, const int* in_sizes, int n_in,
                              void* d_out, int out_size) {
    const float* x      = (const float*)d_in[0];
    const int*   weight = (const int*)d_in[1];
    const int*   table  = (const int*)d_in[2];
    float*       out    = (float*)d_out;

    cudaFuncSetAttribute(pot_kernel, cudaFuncAttributeMaxDynamicSharedMemorySize, SMEM_TOTAL);

    cudaMemsetAsync(out, 0, (size_t)out_size * sizeof(float), 0);               // 1
    init_kernel<<<(B_ * TP_ + 255) / 256, 256>>>();                             // 2
    prepass_kernel<<<(B_ * S_ * (T_ / 4) + 255) / 256, 256>>>((const float4*)x);// 3
    pad_oh_kernel<<<(N_ * S_ + 255) / 256, 256>>>(weight);                      // 4

    pot_kernel<<<GRID_, THREADS_, SMEM_TOTAL>>>(table);                         // 5 -> profiled

    scan_kernel<<<B_, 32>>>(out);                                               // 6
}